// round 12
// baseline (speedup 1.0000x reference)
#include <cuda_runtime.h>
#include <math.h>

#define BB 32
#define NANCH 24564
#define NCLS 81
#define FG 80
#define PRE 200
#define MAXD 100
#define NBINS 64
#define CAP 1024
#define CAP2 2048
#define NPAIR (BB*FG)
#define SLICES 74
#define PER ((NANCH + SLICES - 1) / SLICES)
#define YFLOOR (-3.2f)
#define BINSCALE (64.0f / 3.2f)
#define MW 8   // u32 words per bitmask row (200 bits -> 7 used, pad to 8)
#define NTILE 28

// tile list: (r,w) with 0 <= r <= w <= 6, round-robin dealt to 8 warps
__constant__ int c_tr[NTILE] = {0,0,0,0,0,0,0,1,1,1,1,1,1,2,2,2,2,2,3,3,3,3,4,4,4,5,5,6};
__constant__ int c_tw[NTILE] = {0,1,2,3,4,5,6,1,2,3,4,5,6,2,3,4,5,6,3,4,5,6,4,5,6,5,6,6};

// ---------------- static device scratch ----------------
__device__ int   g_hist[NPAIR*NBINS];
__device__ int   g_binstop[NPAIR];
__device__ int   g_cnt[NPAIR];
__device__ unsigned long long g_buf[(size_t)NPAIR*CAP2];   // 42MB candidate keys
__device__ float g_ksc[NPAIR*MAXD];
__device__ int   g_kslot[NPAIR*MAXD];
__device__ float4 g_kbox[NPAIR*MAXD];
__device__ int   g_kcnt[NPAIR];

__device__ __forceinline__ int binOf(float y) {
    int bi = (int)(__fmul_rn(__fsub_rn(y, YFLOOR), BINSCALE));
    return bi > NBINS-1 ? NBINS-1 : bi;
}

// key: score_bits<<32 | (0x7fff - anchor)<<6 | bin   (sort == (score desc, anchor asc))
__device__ __forceinline__ void emit(int p, float y, int anchor, int bin, int* sh, int f) {
    atomicAdd(&sh[f*NBINS + bin], 1);
    int pos = atomicAdd(&g_cnt[p], 1);
    if (pos < CAP2) {
        unsigned sb = __float_as_uint(expf(y));
        g_buf[(size_t)p*CAP2 + pos] =
            ((unsigned long long)sb << 32) |
            ((unsigned)(0x7fff - anchor) << 6) | (unsigned)bin;
    }
}

// ---------------- K1: softmax reduce (frozen numerics) + histogram + candidate append ----------------
__global__ void __launch_bounds__(256) k1_reduce_hist(const float* __restrict__ logits) {
    __shared__ int sh[FG*NBINS];          // 20KB
    int b = blockIdx.y;
    int a0 = blockIdx.x * PER;
    int a1 = min(a0 + PER, NANCH);
    for (int i = threadIdx.x; i < FG*NBINS; i += 256) sh[i] = 0;
    __syncthreads();
    int w = threadIdx.x >> 5, lane = threadIdx.x & 31;
    const float NEGINF = __int_as_float(0xff800000);
    for (int g = w; a0 + g*4 < a1; g += 8) {
        int a = a0 + g*4;
        int nv = min(a1 - a, 4);
        float x0[4], x1[4], x2[4];
        #pragma unroll
        for (int u = 0; u < 4; u++) {
            int au = a + (u < nv ? u : 0);
            const float* row = logits + (size_t)(b*NANCH + au) * NCLS;
            x0[u] = row[lane];
            x1[u] = row[lane + 32];
            x2[u] = (lane < 17) ? row[lane + 64] : NEGINF;
        }
        float m[4];
        #pragma unroll
        for (int u = 0; u < 4; u++) m[u] = fmaxf(x0[u], fmaxf(x1[u], x2[u]));
        #pragma unroll
        for (int o = 16; o; o >>= 1) {
            #pragma unroll
            for (int u = 0; u < 4; u++)
                m[u] = fmaxf(m[u], __shfl_xor_sync(0xffffffffu, m[u], o));
        }
        float d[4];
        #pragma unroll
        for (int u = 0; u < 4; u++)
            d[u] = expf(x0[u] - m[u]) + expf(x1[u] - m[u]) +
                   ((lane < 17) ? expf(x2[u] - m[u]) : 0.f);
        #pragma unroll
        for (int o = 16; o; o >>= 1) {
            #pragma unroll
            for (int u = 0; u < 4; u++)
                d[u] += __shfl_xor_sync(0xffffffffu, d[u], o);
        }
        float Lc[4];
        #pragma unroll
        for (int u = 0; u < 4; u++) Lc[u] = m[u] + logf(d[u]);
        #pragma unroll
        for (int u = 0; u < 4; u++) {
            if (u >= nv) break;
            int anchor = a + u;
            float y0 = __fsub_rn(x0[u], Lc[u]);
            float y1 = __fsub_rn(x1[u], Lc[u]);
            if (lane >= 1 && y0 > YFLOOR)
                emit(b*FG + (lane-1), y0, anchor, binOf(y0), sh, lane-1);
            if (y1 > YFLOOR)
                emit(b*FG + (lane+31), y1, anchor, binOf(y1), sh, lane+31);
            if (lane < 17) {
                float y2 = __fsub_rn(x2[u], Lc[u]);
                if (y2 > YFLOOR)
                    emit(b*FG + (lane+63), y2, anchor, binOf(y2), sh, lane+63);
            }
        }
    }
    __syncthreads();
    for (int i = threadIdx.x; i < FG*NBINS; i += 256) {
        int v = sh[i];
        if (v) atomicAdd(&g_hist[b*FG*NBINS + i], v);
    }
}

// ---------------- K2: find cutoff bin; zero hist for next replay ----------------
__global__ void k2_cutoff() {
    int p = blockIdx.x * blockDim.x + threadIdx.x;
    if (p >= NPAIR) return;
    int* h = &g_hist[p*NBINS];
    int cum = 0, stop = 0;
    for (int bin = NBINS - 1; bin >= 0; --bin) {
        cum += h[bin];
        if (cum >= PRE) { stop = bin; break; }
    }
    for (int bin = 0; bin < NBINS; ++bin) h[bin] = 0;
    g_binstop[p] = stop;
}

// ---------------- bitonic descending sort in shared memory ----------------
__device__ void bitonic_desc(unsigned long long* keys, int P) {
    for (int k = 2; k <= P; k <<= 1) {
        for (int j = k >> 1; j > 0; j >>= 1) {
            for (int i = threadIdx.x; i < P; i += blockDim.x) {
                int ixj = i ^ j;
                if (ixj > i) {
                    unsigned long long a = keys[i], c = keys[ixj];
                    bool up = ((i & k) == 0);
                    if (up ? (a < c) : (a > c)) { keys[i] = c; keys[ixj] = a; }
                }
            }
            __syncthreads();
        }
    }
}

__device__ __forceinline__ bool iou_gt(float4 kb, float ka, float4 b, float ba) {
    float ix0 = fmaxf(kb.x, b.x), iy0 = fmaxf(kb.y, b.y);
    float ix1 = fminf(kb.z, b.z), iy1 = fminf(kb.w, b.w);
    float iw = fmaxf(ix1 - ix0, 0.f), ih = fmaxf(iy1 - iy0, 0.f);
    float inter = iw * ih;
    float uni = ka + ba - inter;
    return (inter / fmaxf(uni, 1e-9f)) > 0.45f;
}

// ---------------- K4: filter + sort + decode + balanced-tile ballot mask + scan ----------------
__global__ void __launch_bounds__(256, 8) k4_nms(const float* __restrict__ bbox,
                                                 const float* __restrict__ priors) {
    __shared__ unsigned long long keys[CAP];   // 8KB
    __shared__ float4 s_box[PRE];              // 3.2KB
    __shared__ float  s_area[PRE];
    __shared__ float  s_sc[PRE];
    __shared__ unsigned s_M[PRE*MW];           // 6.4KB
    __shared__ int    s_kept[MAXD];
    __shared__ int    s_n;
    int p = blockIdx.x;
    int b = p / FG;
    int cnt0 = g_cnt[p];
    if (cnt0 > CAP2) cnt0 = CAP2;
    int stop = g_binstop[p];
    if (threadIdx.x == 0) s_n = 0;
    __syncthreads();
    // filter candidates by bin >= stop (same set as histogram counted)
    for (int i = threadIdx.x; i < cnt0; i += 256) {
        unsigned long long k = g_buf[(size_t)p*CAP2 + i];
        int bin = (int)(k & 63u);
        if (bin >= stop) {
            int pos = atomicAdd(&s_n, 1);
            if (pos < CAP) keys[pos] = k;
        }
    }
    __syncthreads();
    int cnt = min(s_n, CAP);
    int P = 256;
    while (P < cnt) P <<= 1;
    for (int i = cnt + threadIdx.x; i < P; i += 256) keys[i] = 0ull;
    __syncthreads();
    bitonic_desc(keys, P);

    int lim = min(cnt, PRE);
    // decode top-200 boxes
    for (int t = threadIdx.x; t < PRE; t += 256) {
        float sc = 0.f, ar = 0.f;
        float4 bx = make_float4(0.f, 0.f, 0.f, 0.f);
        if (t < lim) {
            unsigned long long k = keys[t];
            sc = __uint_as_float((unsigned)(k >> 32));
            int a = 0x7fff - (int)(((unsigned)k >> 6) & 0x7fffu);
            float4 loc = *(const float4*)(bbox + (size_t)(b*NANCH + a) * 4);
            float4 pr  = *(const float4*)(priors + (size_t)a * 4);
            float cx = (loc.x * 0.1f) * pr.z + pr.x;
            float cy = (loc.y * 0.1f) * pr.w + pr.y;
            float wd = expf(loc.z * 0.2f) * pr.z;
            float hg = expf(loc.w * 0.2f) * pr.w;
            bx.x = cx - wd * 0.5f; bx.y = cy - hg * 0.5f;
            bx.z = cx + wd * 0.5f; bx.w = cy + hg * 0.5f;
            ar = fmaxf(bx.z - bx.x, 0.f) * fmaxf(bx.w - bx.y, 0.f);
        }
        s_sc[t] = sc; s_box[t] = bx; s_area[t] = ar;
    }
    for (int t = threadIdx.x; t < PRE*MW; t += 256) s_M[t] = 0u;
    __syncthreads();

    // balanced-tile ballot mask build
    {
        int wid = threadIdx.x >> 5;
        int lane = threadIdx.x & 31;
        for (int t = wid; t < NTILE; t += 8) {
            int r = c_tr[t], w = c_tw[t];
            int rowstart = r << 5;
            if (rowstart >= lim) continue;
            int rowend = min(rowstart + 32, lim);
            int jj = (w << 5) + lane;
            bool jvalid = jj < lim;
            int jc = jj < PRE ? jj : PRE - 1;
            float4 bj = s_box[jc];
            float  aj = s_area[jc];
            for (int i = rowstart; i < rowend; i += 2) {
                int i1 = i + 1;
                bool v1 = i1 < rowend;
                int i1c = v1 ? i1 : i;
                float4 b0 = s_box[i];   float a0 = s_area[i];
                float4 b1 = s_box[i1c]; float a1 = s_area[i1c];
                bool sup0 = jvalid && (jj > i)  && iou_gt(b0, a0, bj, aj);
                bool sup1 = jvalid && v1 && (jj > i1) && iou_gt(b1, a1, bj, aj);
                unsigned w0 = __ballot_sync(0xffffffffu, sup0);
                unsigned w1 = __ballot_sync(0xffffffffu, sup1);
                if (lane == 0) {
                    s_M[i*MW + w] = w0;
                    if (v1) s_M[i1*MW + w] = w1;
                }
            }
        }
    }
    __syncthreads();

    // branch-free warp scan
    if (threadIdx.x < 32) {
        int lane = threadIdx.x;
        unsigned supp = 0u;
        int kc = 0;
        for (int i = 0; i < lim && kc < MAXD; i++) {
            unsigned mi = (lane < MW) ? s_M[i*MW + lane] : 0u;
            unsigned wsup = __shfl_sync(0xffffffffu, supp, i >> 5);
            bool keep_i = !((wsup >> (i & 31)) & 1u);
            if (keep_i) {
                supp |= mi;
                if (lane == 0) s_kept[kc] = i;
                kc++;
            }
        }
        __syncwarp();
        for (int t = lane; t < kc; t += 32) {
            int i = s_kept[t];
            g_ksc[p*MAXD + t]   = s_sc[i];
            g_kslot[p*MAXD + t] = i;
            g_kbox[p*MAXD + t]  = s_box[i];
        }
        if (lane == 0) g_kcnt[p] = kc;
    }
    __syncthreads();
    if (threadIdx.x == 0) g_cnt[p] = 0;   // reset for next graph replay
}

// ---------------- K5: per-image top-100 + output ----------------
__global__ void __launch_bounds__(256) k5_topk(float* __restrict__ out) {
    __shared__ int hist[2048];
    __shared__ unsigned long long cand[1024];
    __shared__ int s_kc[FG];
    __shared__ int s_ccnt;
    __shared__ int s_cut;
    int b = blockIdx.x;
    for (int i = threadIdx.x; i < 2048; i += 256) hist[i] = 0;
    for (int i = threadIdx.x; i < FG; i += 256) s_kc[i] = g_kcnt[b*FG + i];
    if (threadIdx.x == 0) s_ccnt = 0;
    __syncthreads();
    for (int eid = threadIdx.x; eid < FG*MAXD; eid += 256) {
        int c = eid / MAXD, t = eid % MAXD;
        if (t < s_kc[c]) {
            unsigned bits = __float_as_uint(g_ksc[(b*FG + c)*MAXD + t]);
            unsigned bi = bits >> 19;
            if (bi > 2047u) bi = 2047u;
            atomicAdd(&hist[bi], 1);
        }
    }
    __syncthreads();
    if (threadIdx.x == 0) {
        int cum = 0, cut = 0;
        for (int bin = 2047; bin >= 0; --bin) {
            cum += hist[bin];
            if (cum >= MAXD) { cut = bin; break; }
        }
        s_cut = cut;
    }
    __syncthreads();
    int cut = s_cut;
    for (int eid = threadIdx.x; eid < FG*MAXD; eid += 256) {
        int c = eid / MAXD, t = eid % MAXD;
        if (t < s_kc[c]) {
            unsigned bits = __float_as_uint(g_ksc[(b*FG + c)*MAXD + t]);
            unsigned bi = bits >> 19;
            if (bi > 2047u) bi = 2047u;
            if ((int)bi >= cut) {
                int pos = atomicAdd(&s_ccnt, 1);
                if (pos < 1024) {
                    int slot = g_kslot[(b*FG + c)*MAXD + t];
                    int flat = c * PRE + slot;
                    unsigned low = ((unsigned)(0x3fff - flat) << 14) | (unsigned)eid;
                    cand[pos] = ((unsigned long long)bits << 32) | low;
                }
            }
        }
    }
    __syncthreads();
    int n = s_ccnt; if (n > 1024) n = 1024;
    int P = 128; while (P < n) P <<= 1;
    for (int i = n + threadIdx.x; i < P; i += 256) cand[i] = 0ull;
    __syncthreads();
    bitonic_desc(cand, P);
    for (int r = threadIdx.x; r < MAXD; r += 256) {
        unsigned long long k = (r < P) ? cand[r] : 0ull;
        float sc = __uint_as_float((unsigned)(k >> 32));
        int eid = (int)((unsigned)k & 0x3fffu);
        int c = eid / MAXD, t = eid % MAXD;
        float4 bx = make_float4(0.f, 0.f, 0.f, 0.f);
        float lb = 1.f;
        if (k != 0ull) {
            bx = g_kbox[(b*FG + c)*MAXD + t];
            lb = (float)(c + 1);
        } else {
            sc = 0.f;
        }
        size_t base = (size_t)(b*MAXD + r);
        out[base*4 + 0] = bx.x;
        out[base*4 + 1] = bx.y;
        out[base*4 + 2] = bx.z;
        out[base*4 + 3] = bx.w;
        out[(size_t)BB*MAXD*4 + base] = sc;
        out[(size_t)BB*MAXD*5 + base] = lb;
    }
}

// ---------------- launch ----------------
extern "C" void kernel_launch(void* const* d_in, const int* in_sizes, int n_in,
                              void* d_out, int out_size) {
    const float* logits = (const float*)d_in[0];
    const float* bbox   = (const float*)d_in[1];
    const float* priors = (const float*)d_in[2];
    float* out = (float*)d_out;

    k1_reduce_hist<<<dim3(SLICES, BB), 256>>>(logits);
    k2_cutoff<<<(NPAIR + 255)/256, 256>>>();
    k4_nms<<<NPAIR, 256>>>(bbox, priors);
    k5_topk<<<BB, 256>>>(out);
}

// round 13
// speedup vs baseline: 1.2000x; 1.2000x over previous
#include <cuda_runtime.h>
#include <math.h>

#define BB 32
#define NANCH 24564
#define NCLS 81
#define FG 80
#define PRE 200
#define MAXD 100
#define NBINS 64
#define CAP 1024
#define NPAIR (BB*FG)
#define SLICES 74
#define PER ((NANCH + SLICES - 1) / SLICES)
#define YFLOOR (-3.2f)
#define BINSCALE (64.0f / 3.2f)
#define MW 8
#define NTILE 28

// tile list: (r,w) with 0 <= r <= w <= 6, round-robin dealt to 8 warps
__constant__ int c_tr[NTILE] = {0,0,0,0,0,0,0,1,1,1,1,1,1,2,2,2,2,2,3,3,3,3,4,4,4,5,5,6};
__constant__ int c_tw[NTILE] = {0,1,2,3,4,5,6,1,2,3,4,5,6,2,3,4,5,6,3,4,5,6,4,5,6,5,6,6};

// ---------------- static device scratch ----------------
__device__ float g_Lc[BB*NANCH];
__device__ int   g_hist[NPAIR*NBINS];
__device__ int   g_binstop[NPAIR];
__device__ int   g_cnt[NPAIR];
__device__ unsigned long long g_key[(size_t)NPAIR*CAP];
__device__ float g_ksc[NPAIR*MAXD];
__device__ int   g_kslot[NPAIR*MAXD];
__device__ float4 g_kbox[NPAIR*MAXD];
__device__ int   g_kcnt[NPAIR];

__device__ __forceinline__ int binOf(float y) {
    int bi = (int)(__fmul_rn(__fsub_rn(y, YFLOOR), BINSCALE));
    return bi > NBINS-1 ? NBINS-1 : bi;
}

// ---------------- K1: softmax reduce (frozen numerics) + histogram, ILP x4 ----------------
__global__ void __launch_bounds__(256) k1_reduce_hist(const float* __restrict__ logits) {
    __shared__ int sh[FG*NBINS];          // 20KB
    int b = blockIdx.y;
    int a0 = blockIdx.x * PER;
    int a1 = min(a0 + PER, NANCH);
    for (int i = threadIdx.x; i < FG*NBINS; i += 256) sh[i] = 0;
    __syncthreads();
    int w = threadIdx.x >> 5, lane = threadIdx.x & 31;
    const float NEGINF = __int_as_float(0xff800000);
    for (int g = w; a0 + g*4 < a1; g += 8) {
        int a = a0 + g*4;
        int nv = min(a1 - a, 4);
        float x0[4], x1[4], x2[4];
        #pragma unroll
        for (int u = 0; u < 4; u++) {
            int au = a + (u < nv ? u : 0);
            const float* row = logits + (size_t)(b*NANCH + au) * NCLS;
            x0[u] = row[lane];
            x1[u] = row[lane + 32];
            x2[u] = (lane < 17) ? row[lane + 64] : NEGINF;
        }
        float m[4];
        #pragma unroll
        for (int u = 0; u < 4; u++) m[u] = fmaxf(x0[u], fmaxf(x1[u], x2[u]));
        #pragma unroll
        for (int o = 16; o; o >>= 1) {
            #pragma unroll
            for (int u = 0; u < 4; u++)
                m[u] = fmaxf(m[u], __shfl_xor_sync(0xffffffffu, m[u], o));
        }
        float d[4];
        #pragma unroll
        for (int u = 0; u < 4; u++)
            d[u] = expf(x0[u] - m[u]) + expf(x1[u] - m[u]) +
                   ((lane < 17) ? expf(x2[u] - m[u]) : 0.f);
        #pragma unroll
        for (int o = 16; o; o >>= 1) {
            #pragma unroll
            for (int u = 0; u < 4; u++)
                d[u] += __shfl_xor_sync(0xffffffffu, d[u], o);
        }
        float Lc[4];
        #pragma unroll
        for (int u = 0; u < 4; u++) Lc[u] = m[u] + logf(d[u]);
        if (lane == 0) {
            #pragma unroll
            for (int u = 0; u < 4; u++)
                if (u < nv) g_Lc[b*NANCH + a + u] = Lc[u];
        }
        #pragma unroll
        for (int u = 0; u < 4; u++) {
            if (u >= nv) break;
            float y0 = __fsub_rn(x0[u], Lc[u]);
            float y1 = __fsub_rn(x1[u], Lc[u]);
            if (lane >= 1 && y0 > YFLOOR) atomicAdd(&sh[(lane-1)*NBINS + binOf(y0)], 1);
            if (y1 > YFLOOR)              atomicAdd(&sh[(lane+31)*NBINS + binOf(y1)], 1);
            if (lane < 17) {
                float y2 = __fsub_rn(x2[u], Lc[u]);
                if (y2 > YFLOOR) atomicAdd(&sh[(lane+63)*NBINS + binOf(y2)], 1);
            }
        }
    }
    __syncthreads();
    for (int i = threadIdx.x; i < FG*NBINS; i += 256) {
        int v = sh[i];
        if (v) atomicAdd(&g_hist[b*FG*NBINS + i], v);
    }
}

// ---------------- K2: find cutoff bin; zero hist for next replay; zero counters ----------------
__global__ void k2_cutoff() {
    int p = blockIdx.x * blockDim.x + threadIdx.x;
    if (p >= NPAIR) return;
    int* h = &g_hist[p*NBINS];
    int cum = 0, stop = 0;
    for (int bin = NBINS - 1; bin >= 0; --bin) {
        cum += h[bin];
        if (cum >= PRE) { stop = bin; break; }
    }
    for (int bin = 0; bin < NBINS; ++bin) h[bin] = 0;
    g_binstop[p] = stop;
    g_cnt[p] = 0;
}

// ---------------- K3: gather candidates (ILP x4, packed keys) ----------------
__global__ void __launch_bounds__(256) k3_gather(const float* __restrict__ logits) {
    __shared__ int s_stop[FG];
    int b = blockIdx.y;
    for (int i = threadIdx.x; i < FG; i += 256) s_stop[i] = g_binstop[b*FG + i];
    __syncthreads();
    int a0 = blockIdx.x * PER;
    int a1 = min(a0 + PER, NANCH);
    int w = threadIdx.x >> 5, lane = threadIdx.x & 31;
    for (int g = w; a0 + g*4 < a1; g += 8) {
        int a = a0 + g*4;
        int nv = min(a1 - a, 4);
        float x0[4], x1[4], x2[4], Lc[4];
        #pragma unroll
        for (int u = 0; u < 4; u++) {
            int au = a + (u < nv ? u : 0);
            const float* row = logits + (size_t)(b*NANCH + au) * NCLS;
            Lc[u] = g_Lc[b*NANCH + au];
            x0[u] = row[lane];
            x1[u] = row[lane + 32];
            x2[u] = (lane < 17) ? row[lane + 64] : -1e30f;
        }
        #pragma unroll
        for (int u = 0; u < 4; u++) {
            if (u >= nv) break;
            float ys[3];
            ys[0] = __fsub_rn(x0[u], Lc[u]);
            ys[1] = __fsub_rn(x1[u], Lc[u]);
            ys[2] = __fsub_rn(x2[u], Lc[u]);
            int fs[3];
            fs[0] = lane - 1;
            fs[1] = lane + 31;
            fs[2] = (lane < 17) ? (lane + 63) : -1;
            #pragma unroll
            for (int e = 0; e < 3; e++) {
                int f = fs[e];
                if (f < 0) continue;
                float y = ys[e];
                if (y > YFLOOR) {
                    int bin = binOf(y);
                    if (bin >= s_stop[f]) {
                        int p = b*FG + f;
                        int pos = atomicAdd(&g_cnt[p], 1);
                        if (pos < CAP) {
                            unsigned sb = __float_as_uint(expf(y));
                            g_key[(size_t)p*CAP + pos] =
                                ((unsigned long long)sb << 32) |
                                (0xffffffffu - (unsigned)(a + u));
                        }
                    }
                }
            }
        }
    }
}

// ---------------- bitonic descending sort in shared memory ----------------
__device__ void bitonic_desc(unsigned long long* keys, int P) {
    for (int k = 2; k <= P; k <<= 1) {
        for (int j = k >> 1; j > 0; j >>= 1) {
            for (int i = threadIdx.x; i < P; i += blockDim.x) {
                int ixj = i ^ j;
                if (ixj > i) {
                    unsigned long long a = keys[i], c = keys[ixj];
                    bool up = ((i & k) == 0);
                    if (up ? (a < c) : (a > c)) { keys[i] = c; keys[ixj] = a; }
                }
            }
            __syncthreads();
        }
    }
}

__device__ __forceinline__ bool iou_gt(float4 kb, float ka, float4 b, float ba) {
    float ix0 = fmaxf(kb.x, b.x), iy0 = fmaxf(kb.y, b.y);
    float ix1 = fminf(kb.z, b.z), iy1 = fminf(kb.w, b.w);
    float iw = fmaxf(ix1 - ix0, 0.f), ih = fmaxf(iy1 - iy0, 0.f);
    float inter = iw * ih;
    float uni = ka + ba - inter;
    return (inter / fmaxf(uni, 1e-9f)) > 0.45f;
}

// ---------------- K4: sort + decode + specialized balanced-tile ballot mask + scan ----------------
__global__ void __launch_bounds__(256, 8) k4_nms(const float* __restrict__ bbox,
                                                 const float* __restrict__ priors) {
    __shared__ unsigned long long keys[CAP];   // 8KB
    __shared__ float4 s_box[PRE];
    __shared__ float  s_area[PRE];
    __shared__ float  s_sc[PRE];
    __shared__ unsigned s_M[PRE*MW];
    __shared__ int    s_kept[MAXD];
    int p = blockIdx.x;
    int b = p / FG;
    int cnt = g_cnt[p];
    if (cnt > CAP) cnt = CAP;
    int P = 256;
    while (P < cnt) P <<= 1;
    for (int i = threadIdx.x; i < P; i += 256)
        keys[i] = (i < cnt) ? g_key[(size_t)p*CAP + i] : 0ull;
    __syncthreads();
    bitonic_desc(keys, P);

    int lim = min(cnt, PRE);
    for (int t = threadIdx.x; t < PRE; t += 256) {
        float sc = 0.f, ar = 0.f;
        float4 bx = make_float4(0.f, 0.f, 0.f, 0.f);
        if (t < lim) {
            unsigned long long k = keys[t];
            sc = __uint_as_float((unsigned)(k >> 32));
            int a = (int)(0xffffffffu - (unsigned)k);
            float4 loc = *(const float4*)(bbox + (size_t)(b*NANCH + a) * 4);
            float4 pr  = *(const float4*)(priors + (size_t)a * 4);
            float cx = (loc.x * 0.1f) * pr.z + pr.x;
            float cy = (loc.y * 0.1f) * pr.w + pr.y;
            float wd = expf(loc.z * 0.2f) * pr.z;
            float hg = expf(loc.w * 0.2f) * pr.w;
            bx.x = cx - wd * 0.5f; bx.y = cy - hg * 0.5f;
            bx.z = cx + wd * 0.5f; bx.w = cy + hg * 0.5f;
            ar = fmaxf(bx.z - bx.x, 0.f) * fmaxf(bx.w - bx.y, 0.f);
        }
        s_sc[t] = sc; s_box[t] = bx; s_area[t] = ar;
    }
    for (int t = threadIdx.x; t < PRE*MW; t += 256) s_M[t] = 0u;
    __syncthreads();

    // balanced-tile ballot mask build, specialized per tile type
    {
        int wid = threadIdx.x >> 5;
        int lane = threadIdx.x & 31;
        for (int t = wid; t < NTILE; t += 8) {
            int r = c_tr[t], w = c_tw[t];
            int rowstart = r << 5;
            if (rowstart >= lim) continue;
            int rowend = min(rowstart + 32, lim);
            int jj = (w << 5) + lane;
            bool jvalid = jj < lim;
            int jc = jj < PRE ? jj : PRE - 1;
            float4 bj = s_box[jc];
            float  aj = s_area[jc];
            if (r == w) {
                // diagonal tile: jj > i test required
                for (int i = rowstart; i < rowend; i++) {
                    bool sup = jvalid && (jj > i) && iou_gt(s_box[i], s_area[i], bj, aj);
                    unsigned wd = __ballot_sync(0xffffffffu, sup);
                    if (lane == 0) s_M[i*MW + w] = wd;
                }
            } else if (rowend == rowstart + 32) {
                // full off-diagonal tile: jj > i always true; clean ILP x2
                #pragma unroll
                for (int i = rowstart; i < rowstart + 32; i += 2) {
                    float4 b0 = s_box[i];     float a0 = s_area[i];
                    float4 b1 = s_box[i + 1]; float a1 = s_area[i + 1];
                    bool sup0 = jvalid && iou_gt(b0, a0, bj, aj);
                    bool sup1 = jvalid && iou_gt(b1, a1, bj, aj);
                    unsigned w0 = __ballot_sync(0xffffffffu, sup0);
                    unsigned w1 = __ballot_sync(0xffffffffu, sup1);
                    if (lane == 0) {
                        s_M[i*MW + w] = w0;
                        s_M[(i+1)*MW + w] = w1;
                    }
                }
            } else {
                // partial off-diagonal tile
                for (int i = rowstart; i < rowend; i++) {
                    bool sup = jvalid && iou_gt(s_box[i], s_area[i], bj, aj);
                    unsigned wd = __ballot_sync(0xffffffffu, sup);
                    if (lane == 0) s_M[i*MW + w] = wd;
                }
            }
        }
    }
    __syncthreads();

    // branch-free warp scan
    if (threadIdx.x < 32) {
        int lane = threadIdx.x;
        unsigned supp = 0u;
        int kc = 0;
        for (int i = 0; i < lim && kc < MAXD; i++) {
            unsigned mi = (lane < MW) ? s_M[i*MW + lane] : 0u;
            unsigned wsup = __shfl_sync(0xffffffffu, supp, i >> 5);
            bool keep_i = !((wsup >> (i & 31)) & 1u);
            if (keep_i) {
                supp |= mi;
                if (lane == 0) s_kept[kc] = i;
                kc++;
            }
        }
        __syncwarp();
        for (int t = lane; t < kc; t += 32) {
            int i = s_kept[t];
            g_ksc[p*MAXD + t]   = s_sc[i];
            g_kslot[p*MAXD + t] = i;
            g_kbox[p*MAXD + t]  = s_box[i];
        }
        if (lane == 0) g_kcnt[p] = kc;
    }
}

// ---------------- K5: per-image top-100 + output (two-level cutoff scan) ----------------
__global__ void __launch_bounds__(256) k5_topk(float* __restrict__ out) {
    __shared__ int hist[2048];
    __shared__ int s_chunk[256];
    __shared__ unsigned long long cand[1024];
    __shared__ int s_kc[FG];
    __shared__ int s_ccnt;
    __shared__ int s_cut;
    int b = blockIdx.x;
    for (int i = threadIdx.x; i < 2048; i += 256) hist[i] = 0;
    for (int i = threadIdx.x; i < FG; i += 256) s_kc[i] = g_kcnt[b*FG + i];
    if (threadIdx.x == 0) { s_ccnt = 0; s_cut = 0; }
    __syncthreads();
    for (int eid = threadIdx.x; eid < FG*MAXD; eid += 256) {
        int c = eid / MAXD, t = eid % MAXD;
        if (t < s_kc[c]) {
            unsigned bits = __float_as_uint(g_ksc[(b*FG + c)*MAXD + t]);
            unsigned bi = bits >> 19;
            if (bi > 2047u) bi = 2047u;
            atomicAdd(&hist[bi], 1);
        }
    }
    __syncthreads();
    // two-level cutoff: per-thread 8-bin chunk sums, then short serial scans
    {
        int base = threadIdx.x << 3;
        int s = 0;
        #pragma unroll
        for (int k = 0; k < 8; k++) s += hist[base + k];
        s_chunk[threadIdx.x] = s;
    }
    __syncthreads();
    if (threadIdx.x == 0) {
        int cum = 0;
        for (int c = 255; c >= 0; --c) {
            int cs = s_chunk[c];
            if (cum + cs >= MAXD) {
                int cc = cum;
                int cut = c << 3;
                for (int bin = (c << 3) + 7; bin >= (c << 3); --bin) {
                    cc += hist[bin];
                    if (cc >= MAXD) { cut = bin; break; }
                }
                s_cut = cut;
                break;
            }
            cum += cs;
        }
    }
    __syncthreads();
    int cut = s_cut;
    for (int eid = threadIdx.x; eid < FG*MAXD; eid += 256) {
        int c = eid / MAXD, t = eid % MAXD;
        if (t < s_kc[c]) {
            unsigned bits = __float_as_uint(g_ksc[(b*FG + c)*MAXD + t]);
            unsigned bi = bits >> 19;
            if (bi > 2047u) bi = 2047u;
            if ((int)bi >= cut) {
                int pos = atomicAdd(&s_ccnt, 1);
                if (pos < 1024) {
                    int slot = g_kslot[(b*FG + c)*MAXD + t];
                    int flat = c * PRE + slot;
                    unsigned low = ((unsigned)(0x3fff - flat) << 14) | (unsigned)eid;
                    cand[pos] = ((unsigned long long)bits << 32) | low;
                }
            }
        }
    }
    __syncthreads();
    int n = s_ccnt; if (n > 1024) n = 1024;
    int P = 128; while (P < n) P <<= 1;
    for (int i = n + threadIdx.x; i < P; i += 256) cand[i] = 0ull;
    __syncthreads();
    bitonic_desc(cand, P);
    for (int r = threadIdx.x; r < MAXD; r += 256) {
        unsigned long long k = (r < P) ? cand[r] : 0ull;
        float sc = __uint_as_float((unsigned)(k >> 32));
        int eid = (int)((unsigned)k & 0x3fffu);
        int c = eid / MAXD, t = eid % MAXD;
        float4 bx = make_float4(0.f, 0.f, 0.f, 0.f);
        float lb = 1.f;
        if (k != 0ull) {
            bx = g_kbox[(b*FG + c)*MAXD + t];
            lb = (float)(c + 1);
        } else {
            sc = 0.f;
        }
        size_t base = (size_t)(b*MAXD + r);
        out[base*4 + 0] = bx.x;
        out[base*4 + 1] = bx.y;
        out[base*4 + 2] = bx.z;
        out[base*4 + 3] = bx.w;
        out[(size_t)BB*MAXD*4 + base] = sc;
        out[(size_t)BB*MAXD*5 + base] = lb;
    }
}

// ---------------- launch ----------------
extern "C" void kernel_launch(void* const* d_in, const int* in_sizes, int n_in,
                              void* d_out, int out_size) {
    const float* logits = (const float*)d_in[0];
    const float* bbox   = (const float*)d_in[1];
    const float* priors = (const float*)d_in[2];
    float* out = (float*)d_out;

    k1_reduce_hist<<<dim3(SLICES, BB), 256>>>(logits);
    k2_cutoff<<<(NPAIR + 255)/256, 256>>>();
    k3_gather<<<dim3(SLICES, BB), 256>>>(logits);
    k4_nms<<<NPAIR, 256>>>(bbox, priors);
    k5_topk<<<BB, 256>>>(out);
}

// round 15
// speedup vs baseline: 1.2584x; 1.0487x over previous
#include <cuda_runtime.h>
#include <math.h>

#define BB 32
#define NANCH 24564
#define NCLS 81
#define FG 80
#define PRE 200
#define MAXD 100
#define NBINS 64
#define CAP 1024
#define NPAIR (BB*FG)
#define SLICES 74
#define PER ((NANCH + SLICES - 1) / SLICES)
#define YFLOOR (-3.2f)
#define BINSCALE (64.0f / 3.2f)
#define MW 8
#define NTILE 28

// tile list: (r,w) with 0 <= r <= w <= 6, round-robin dealt to 8 warps
__constant__ int c_tr[NTILE] = {0,0,0,0,0,0,0,1,1,1,1,1,1,2,2,2,2,2,3,3,3,3,4,4,4,5,5,6};
__constant__ int c_tw[NTILE] = {0,1,2,3,4,5,6,1,2,3,4,5,6,2,3,4,5,6,3,4,5,6,4,5,6,5,6,6};

// ---------------- static device scratch ----------------
__device__ float g_Lc[BB*NANCH];
__device__ int   g_hist[NPAIR*NBINS];
__device__ int   g_binstop[NPAIR];
__device__ int   g_cnt[NPAIR];
__device__ unsigned long long g_key[(size_t)NPAIR*CAP];
__device__ float g_ksc[NPAIR*MAXD];
__device__ int   g_kslot[NPAIR*MAXD];
__device__ float4 g_kbox[NPAIR*MAXD];
__device__ int   g_kcnt[NPAIR];

__device__ __forceinline__ int binOf(float y) {
    int bi = (int)(__fmul_rn(__fsub_rn(y, YFLOOR), BINSCALE));
    return bi > NBINS-1 ? NBINS-1 : bi;
}

// ---------------- K1: softmax reduce (frozen numerics) + histogram, ILP x4 ----------------
__global__ void __launch_bounds__(256) k1_reduce_hist(const float* __restrict__ logits) {
    __shared__ int sh[FG*NBINS];          // 20KB
    int b = blockIdx.y;
    int a0 = blockIdx.x * PER;
    int a1 = min(a0 + PER, NANCH);
    for (int i = threadIdx.x; i < FG*NBINS; i += 256) sh[i] = 0;
    __syncthreads();
    int w = threadIdx.x >> 5, lane = threadIdx.x & 31;
    const float NEGINF = __int_as_float(0xff800000);
    for (int g = w; a0 + g*4 < a1; g += 8) {
        int a = a0 + g*4;
        int nv = min(a1 - a, 4);
        float x0[4], x1[4], x2[4];
        #pragma unroll
        for (int u = 0; u < 4; u++) {
            int au = a + (u < nv ? u : 0);
            const float* row = logits + (size_t)(b*NANCH + au) * NCLS;
            x0[u] = row[lane];
            x1[u] = row[lane + 32];
            x2[u] = (lane < 17) ? row[lane + 64] : NEGINF;
        }
        float m[4];
        #pragma unroll
        for (int u = 0; u < 4; u++) m[u] = fmaxf(x0[u], fmaxf(x1[u], x2[u]));
        #pragma unroll
        for (int o = 16; o; o >>= 1) {
            #pragma unroll
            for (int u = 0; u < 4; u++)
                m[u] = fmaxf(m[u], __shfl_xor_sync(0xffffffffu, m[u], o));
        }
        float d[4];
        #pragma unroll
        for (int u = 0; u < 4; u++)
            d[u] = expf(x0[u] - m[u]) + expf(x1[u] - m[u]) +
                   ((lane < 17) ? expf(x2[u] - m[u]) : 0.f);
        #pragma unroll
        for (int o = 16; o; o >>= 1) {
            #pragma unroll
            for (int u = 0; u < 4; u++)
                d[u] += __shfl_xor_sync(0xffffffffu, d[u], o);
        }
        float Lc[4];
        #pragma unroll
        for (int u = 0; u < 4; u++) Lc[u] = m[u] + logf(d[u]);
        if (lane == 0) {
            #pragma unroll
            for (int u = 0; u < 4; u++)
                if (u < nv) g_Lc[b*NANCH + a + u] = Lc[u];
        }
        #pragma unroll
        for (int u = 0; u < 4; u++) {
            if (u >= nv) break;
            float y0 = __fsub_rn(x0[u], Lc[u]);
            float y1 = __fsub_rn(x1[u], Lc[u]);
            if (lane >= 1 && y0 > YFLOOR) atomicAdd(&sh[(lane-1)*NBINS + binOf(y0)], 1);
            if (y1 > YFLOOR)              atomicAdd(&sh[(lane+31)*NBINS + binOf(y1)], 1);
            if (lane < 17) {
                float y2 = __fsub_rn(x2[u], Lc[u]);
                if (y2 > YFLOOR) atomicAdd(&sh[(lane+63)*NBINS + binOf(y2)], 1);
            }
        }
    }
    __syncthreads();
    for (int i = threadIdx.x; i < FG*NBINS; i += 256) {
        int v = sh[i];
        if (v) atomicAdd(&g_hist[b*FG*NBINS + i], v);
    }
}

// ---------------- K2: find cutoff bin; zero hist for next replay; zero counters ----------------
__global__ void k2_cutoff() {
    int p = blockIdx.x * blockDim.x + threadIdx.x;
    if (p >= NPAIR) return;
    int* h = &g_hist[p*NBINS];
    int cum = 0, stop = 0;
    for (int bin = NBINS - 1; bin >= 0; --bin) {
        cum += h[bin];
        if (cum >= PRE) { stop = bin; break; }
    }
    for (int bin = 0; bin < NBINS; ++bin) h[bin] = 0;
    g_binstop[p] = stop;
    g_cnt[p] = 0;
}

// ---------------- K3: gather candidates (ILP x4, packed keys) ----------------
__global__ void __launch_bounds__(256) k3_gather(const float* __restrict__ logits) {
    __shared__ int s_stop[FG];
    int b = blockIdx.y;
    for (int i = threadIdx.x; i < FG; i += 256) s_stop[i] = g_binstop[b*FG + i];
    __syncthreads();
    int a0 = blockIdx.x * PER;
    int a1 = min(a0 + PER, NANCH);
    int w = threadIdx.x >> 5, lane = threadIdx.x & 31;
    for (int g = w; a0 + g*4 < a1; g += 8) {
        int a = a0 + g*4;
        int nv = min(a1 - a, 4);
        float x0[4], x1[4], x2[4], Lc[4];
        #pragma unroll
        for (int u = 0; u < 4; u++) {
            int au = a + (u < nv ? u : 0);
            const float* row = logits + (size_t)(b*NANCH + au) * NCLS;
            Lc[u] = g_Lc[b*NANCH + au];
            x0[u] = row[lane];
            x1[u] = row[lane + 32];
            x2[u] = (lane < 17) ? row[lane + 64] : -1e30f;
        }
        #pragma unroll
        for (int u = 0; u < 4; u++) {
            if (u >= nv) break;
            float ys[3];
            ys[0] = __fsub_rn(x0[u], Lc[u]);
            ys[1] = __fsub_rn(x1[u], Lc[u]);
            ys[2] = __fsub_rn(x2[u], Lc[u]);
            int fs[3];
            fs[0] = lane - 1;
            fs[1] = lane + 31;
            fs[2] = (lane < 17) ? (lane + 63) : -1;
            #pragma unroll
            for (int e = 0; e < 3; e++) {
                int f = fs[e];
                if (f < 0) continue;
                float y = ys[e];
                if (y > YFLOOR) {
                    int bin = binOf(y);
                    if (bin >= s_stop[f]) {
                        int p = b*FG + f;
                        int pos = atomicAdd(&g_cnt[p], 1);
                        if (pos < CAP) {
                            unsigned sb = __float_as_uint(expf(y));
                            g_key[(size_t)p*CAP + pos] =
                                ((unsigned long long)sb << 32) |
                                (0xffffffffu - (unsigned)(a + u));
                        }
                    }
                }
            }
        }
    }
}

// ---------------- bitonic descending sort in shared memory (fallback path) ----------------
__device__ void bitonic_desc(unsigned long long* keys, int P) {
    for (int k = 2; k <= P; k <<= 1) {
        for (int j = k >> 1; j > 0; j >>= 1) {
            for (int i = threadIdx.x; i < P; i += blockDim.x) {
                int ixj = i ^ j;
                if (ixj > i) {
                    unsigned long long a = keys[i], c = keys[ixj];
                    bool up = ((i & k) == 0);
                    if (up ? (a < c) : (a > c)) { keys[i] = c; keys[ixj] = a; }
                }
            }
            __syncthreads();
        }
    }
}

// register-resident compare-exchange via shfl (j < 32)
__device__ __forceinline__ void bsw_shfl(unsigned long long& v, int j, int k, int tid) {
    unsigned long long pv = __shfl_xor_sync(0xffffffffu, v, j);
    bool up = ((tid & k) == 0);
    bool lower = ((tid & j) == 0);
    bool takemax = (up == lower);
    bool gt = v > pv;
    v = (takemax == gt) ? v : pv;
}

__device__ __forceinline__ bool iou_gt(float4 kb, float ka, float4 b, float ba) {
    float ix0 = fmaxf(kb.x, b.x), iy0 = fmaxf(kb.y, b.y);
    float ix1 = fminf(kb.z, b.z), iy1 = fminf(kb.w, b.w);
    float iw = fmaxf(ix1 - ix0, 0.f), ih = fmaxf(iy1 - iy0, 0.f);
    float inter = iw * ih;
    float uni = ka + ba - inter;
    return (inter / fmaxf(uni, 1e-9f)) > 0.45f;
}

// ---------------- K4: register-bitonic sort + decode + tile ballot mask + scan ----------------
__global__ void __launch_bounds__(256, 8) k4_nms(const float* __restrict__ bbox,
                                                 const float* __restrict__ priors) {
    __shared__ unsigned long long keys[CAP];   // 8KB
    __shared__ float4 s_box[PRE];
    __shared__ float  s_area[PRE];
    __shared__ float  s_sc[PRE];
    __shared__ unsigned s_M[PRE*MW];
    __shared__ int    s_kept[MAXD];
    int p = blockIdx.x;
    int b = p / FG;
    int tid = threadIdx.x;
    int cnt = g_cnt[p];
    if (cnt > CAP) cnt = CAP;

    if (cnt <= 256) {
        // fast path: 1 key/thread register bitonic, shfl for j<32, smem for j>=32
        unsigned long long v = (tid < cnt) ? g_key[(size_t)p*CAP + tid] : 0ull;
        #pragma unroll
        for (int k = 2; k <= 32; k <<= 1)
            #pragma unroll
            for (int j = k >> 1; j; j >>= 1) bsw_shfl(v, j, k, tid);
        #pragma unroll
        for (int k = 64; k <= 256; k <<= 1) {
            #pragma unroll
            for (int j = k >> 1; j >= 32; j >>= 1) {
                keys[tid] = v;
                __syncthreads();
                unsigned long long pv = keys[tid ^ j];
                bool up = ((tid & k) == 0);
                bool lower = ((tid & j) == 0);
                bool takemax = (up == lower);
                bool gt = v > pv;
                v = (takemax == gt) ? v : pv;
                __syncthreads();
            }
            #pragma unroll
            for (int j = 16; j; j >>= 1) bsw_shfl(v, j, k, tid);
        }
        keys[tid] = v;
        __syncthreads();
    } else {
        // fallback: generic smem bitonic
        int P = 512;
        while (P < cnt) P <<= 1;
        for (int i = tid; i < P; i += 256)
            keys[i] = (i < cnt) ? g_key[(size_t)p*CAP + i] : 0ull;
        __syncthreads();
        bitonic_desc(keys, P);
    }

    int lim = min(cnt, PRE);
    for (int t = tid; t < PRE; t += 256) {
        float sc = 0.f, ar = 0.f;
        float4 bx = make_float4(0.f, 0.f, 0.f, 0.f);
        if (t < lim) {
            unsigned long long k = keys[t];
            sc = __uint_as_float((unsigned)(k >> 32));
            int a = (int)(0xffffffffu - (unsigned)k);
            float4 loc = *(const float4*)(bbox + (size_t)(b*NANCH + a) * 4);
            float4 pr  = *(const float4*)(priors + (size_t)a * 4);
            float cx = (loc.x * 0.1f) * pr.z + pr.x;
            float cy = (loc.y * 0.1f) * pr.w + pr.y;
            float wd = expf(loc.z * 0.2f) * pr.z;
            float hg = expf(loc.w * 0.2f) * pr.w;
            bx.x = cx - wd * 0.5f; bx.y = cy - hg * 0.5f;
            bx.z = cx + wd * 0.5f; bx.w = cy + hg * 0.5f;
            ar = fmaxf(bx.z - bx.x, 0.f) * fmaxf(bx.w - bx.y, 0.f);
        }
        s_sc[t] = sc; s_box[t] = bx; s_area[t] = ar;
    }
    for (int t = tid; t < PRE*MW; t += 256) s_M[t] = 0u;
    __syncthreads();

    // balanced-tile ballot mask build, specialized per tile type
    {
        int wid = tid >> 5;
        int lane = tid & 31;
        for (int t = wid; t < NTILE; t += 8) {
            int r = c_tr[t], w = c_tw[t];
            int rowstart = r << 5;
            if (rowstart >= lim) continue;
            int rowend = min(rowstart + 32, lim);
            int jj = (w << 5) + lane;
            bool jvalid = jj < lim;
            int jc = jj < PRE ? jj : PRE - 1;
            float4 bj = s_box[jc];
            float  aj = s_area[jc];
            if (r == w) {
                for (int i = rowstart; i < rowend; i++) {
                    bool sup = jvalid && (jj > i) && iou_gt(s_box[i], s_area[i], bj, aj);
                    unsigned wd = __ballot_sync(0xffffffffu, sup);
                    if (lane == 0) s_M[i*MW + w] = wd;
                }
            } else if (rowend == rowstart + 32) {
                #pragma unroll
                for (int i = rowstart; i < rowstart + 32; i += 2) {
                    float4 b0 = s_box[i];     float a0 = s_area[i];
                    float4 b1 = s_box[i + 1]; float a1 = s_area[i + 1];
                    bool sup0 = jvalid && iou_gt(b0, a0, bj, aj);
                    bool sup1 = jvalid && iou_gt(b1, a1, bj, aj);
                    unsigned w0 = __ballot_sync(0xffffffffu, sup0);
                    unsigned w1 = __ballot_sync(0xffffffffu, sup1);
                    if (lane == 0) {
                        s_M[i*MW + w] = w0;
                        s_M[(i+1)*MW + w] = w1;
                    }
                }
            } else {
                for (int i = rowstart; i < rowend; i++) {
                    bool sup = jvalid && iou_gt(s_box[i], s_area[i], bj, aj);
                    unsigned wd = __ballot_sync(0xffffffffu, sup);
                    if (lane == 0) s_M[i*MW + w] = wd;
                }
            }
        }
    }
    __syncthreads();

    // branch-free warp scan
    if (tid < 32) {
        int lane = tid;
        unsigned supp = 0u;
        int kc = 0;
        for (int i = 0; i < lim && kc < MAXD; i++) {
            unsigned mi = (lane < MW) ? s_M[i*MW + lane] : 0u;
            unsigned wsup = __shfl_sync(0xffffffffu, supp, i >> 5);
            bool keep_i = !((wsup >> (i & 31)) & 1u);
            if (keep_i) {
                supp |= mi;
                if (lane == 0) s_kept[kc] = i;
                kc++;
            }
        }
        __syncwarp();
        for (int t = lane; t < kc; t += 32) {
            int i = s_kept[t];
            g_ksc[p*MAXD + t]   = s_sc[i];
            g_kslot[p*MAXD + t] = i;
            g_kbox[p*MAXD + t]  = s_box[i];
        }
        if (lane == 0) g_kcnt[p] = kc;
    }
}

// ---------------- K5: per-image top-100 + output (two-level cutoff scan) ----------------
__global__ void __launch_bounds__(256) k5_topk(float* __restrict__ out) {
    __shared__ int hist[2048];
    __shared__ int s_chunk[256];
    __shared__ unsigned long long cand[1024];
    __shared__ int s_kc[FG];
    __shared__ int s_ccnt;
    __shared__ int s_cut;
    int b = blockIdx.x;
    for (int i = threadIdx.x; i < 2048; i += 256) hist[i] = 0;
    for (int i = threadIdx.x; i < FG; i += 256) s_kc[i] = g_kcnt[b*FG + i];
    if (threadIdx.x == 0) { s_ccnt = 0; s_cut = 0; }
    __syncthreads();
    for (int eid = threadIdx.x; eid < FG*MAXD; eid += 256) {
        int c = eid / MAXD, t = eid % MAXD;
        if (t < s_kc[c]) {
            unsigned bits = __float_as_uint(g_ksc[(b*FG + c)*MAXD + t]);
            unsigned bi = bits >> 19;
            if (bi > 2047u) bi = 2047u;
            atomicAdd(&hist[bi], 1);
        }
    }
    __syncthreads();
    {
        int base = threadIdx.x << 3;
        int s = 0;
        #pragma unroll
        for (int k = 0; k < 8; k++) s += hist[base + k];
        s_chunk[threadIdx.x] = s;
    }
    __syncthreads();
    if (threadIdx.x == 0) {
        int cum = 0;
        for (int c = 255; c >= 0; --c) {
            int cs = s_chunk[c];
            if (cum + cs >= MAXD) {
                int cc = cum;
                int cut = c << 3;
                for (int bin = (c << 3) + 7; bin >= (c << 3); --bin) {
                    cc += hist[bin];
                    if (cc >= MAXD) { cut = bin; break; }
                }
                s_cut = cut;
                break;
            }
            cum += cs;
        }
    }
    __syncthreads();
    int cut = s_cut;
    for (int eid = threadIdx.x; eid < FG*MAXD; eid += 256) {
        int c = eid / MAXD, t = eid % MAXD;
        if (t < s_kc[c]) {
            unsigned bits = __float_as_uint(g_ksc[(b*FG + c)*MAXD + t]);
            unsigned bi = bits >> 19;
            if (bi > 2047u) bi = 2047u;
            if ((int)bi >= cut) {
                int pos = atomicAdd(&s_ccnt, 1);
                if (pos < 1024) {
                    int slot = g_kslot[(b*FG + c)*MAXD + t];
                    int flat = c * PRE + slot;
                    unsigned low = ((unsigned)(0x3fff - flat) << 14) | (unsigned)eid;
                    cand[pos] = ((unsigned long long)bits << 32) | low;
                }
            }
        }
    }
    __syncthreads();
    int n = s_ccnt; if (n > 1024) n = 1024;
    int P = 128; while (P < n) P <<= 1;
    for (int i = n + threadIdx.x; i < P; i += 256) cand[i] = 0ull;
    __syncthreads();
    bitonic_desc(cand, P);
    for (int r = threadIdx.x; r < MAXD; r += 256) {
        unsigned long long k = (r < P) ? cand[r] : 0ull;
        float sc = __uint_as_float((unsigned)(k >> 32));
        int eid = (int)((unsigned)k & 0x3fffu);
        int c = eid / MAXD, t = eid % MAXD;
        float4 bx = make_float4(0.f, 0.f, 0.f, 0.f);
        float lb = 1.f;
        if (k != 0ull) {
            bx = g_kbox[(b*FG + c)*MAXD + t];
            lb = (float)(c + 1);
        } else {
            sc = 0.f;
        }
        size_t base = (size_t)(b*MAXD + r);
        out[base*4 + 0] = bx.x;
        out[base*4 + 1] = bx.y;
        out[base*4 + 2] = bx.z;
        out[base*4 + 3] = bx.w;
        out[(size_t)BB*MAXD*4 + base] = sc;
        out[(size_t)BB*MAXD*5 + base] = lb;
    }
}

// ---------------- launch ----------------
extern "C" void kernel_launch(void* const* d_in, const int* in_sizes, int n_in,
                              void* d_out, int out_size) {
    const float* logits = (const float*)d_in[0];
    const float* bbox   = (const float*)d_in[1];
    const float* priors = (const float*)d_in[2];
    float* out = (float*)d_out;

    k1_reduce_hist<<<dim3(SLICES, BB), 256>>>(logits);
    k2_cutoff<<<(NPAIR + 255)/256, 256>>>();
    k3_gather<<<dim3(SLICES, BB), 256>>>(logits);
    k4_nms<<<NPAIR, 256>>>(bbox, priors);
    k5_topk<<<BB, 256>>>(out);
}